// round 6
// baseline (speedup 1.0000x reference)
#include <cuda_runtime.h>
#include <math.h>

#define B_SZ     256
#define S_LEN    1024
#define T_LEN    21
#define NFREQ    11
#define NCH      32
#define COUT     64
#define POOL_T   512
#define HID      32
#define NWROWS   46
#define ROWP2    264     /* conv smem row pitch in u64 */
#define XGT      128     /* rows per CTA in xg GEMM */

#define L2E   1.4426950408889634f
#define TL2E  2.8853900817779268f

typedef unsigned long long u64t;

/* ---------------- device scratch (module-static, no runtime alloc) ------ */
__device__ __align__(16) float g_tw[T_LEN * NFREQ * 2];
__device__ __align__(16) float g_L[NWROWS * T_LEN];
__device__ __align__(16) ulonglong2 g_w01[NCH * 32];
__device__ __align__(16) u64t g_w2v[NCH * 32];
__device__ __align__(16) float g_feat[B_SZ * NCH * S_LEN];
__device__ __align__(16) float g_pooled[B_SZ * POOL_T * COUT];
__device__ __align__(16) float g_xg[B_SZ * POOL_T * 128];

__constant__ float c_lo[8] = {
    -0.010597401784997278f,  0.032883011666982945f,  0.030841381835986965f,
    -0.18703481171888114f,  -0.02798376941698385f,   0.6308807679295904f,
     0.7148465705525415f,    0.23037781330885523f };
__constant__ float c_hi[8] = {
    -0.23037781330885523f,   0.7148465705525415f,   -0.6308807679295904f,
    -0.02798376941698385f,   0.18703481171888114f,   0.030841381835986965f,
    -0.032883011666982945f, -0.010597401784997278f };

/* ---------------- packed f32x2 + fast-math helpers ---------------------- */
static __device__ __forceinline__ u64t pk2(float a, float b) {
    u64t r;
    asm("mov.b64 %0,{%1,%2};" : "=l"(r) : "f"(a), "f"(b));
    return r;
}
static __device__ __forceinline__ void upk2(u64t v, float& a, float& b) {
    asm("mov.b64 {%0,%1},%2;" : "=f"(a), "=f"(b) : "l"(v));
}
static __device__ __forceinline__ void ffma2(u64t& d, u64t a, u64t b) {
    asm("fma.rn.f32x2 %0,%1,%2,%0;" : "+l"(d) : "l"(a), "l"(b));
}
static __device__ __forceinline__ void fadd2(u64t& d, u64t a) {
    asm("add.rn.f32x2 %0,%0,%1;" : "+l"(d) : "l"(a));
}
static __device__ __forceinline__ float ex2f(float x) {
    float r; asm("ex2.approx.f32 %0,%1;" : "=f"(r) : "f"(x)); return r;
}
static __device__ __forceinline__ float rcpf(float x) {
    float r; asm("rcp.approx.f32 %0,%1;" : "=f"(r) : "f"(x)); return r;
}
static __device__ __forceinline__ float sig_p(float zp) {   /* z pre-scaled L2E  */
    return rcpf(1.f + ex2f(-zp));
}
static __device__ __forceinline__ float tanh_p(float zp) {  /* z pre-scaled 2L2E */
    return fmaf(2.f, rcpf(1.f + ex2f(-zp)), -1.f);
}

/* ============ K0: twiddles, wavelet map L, paired conv weights =========== */
__global__ void precompute_kernel(const float* __restrict__ conv_w)
{
    int tid = threadIdx.x;

    for (int i = tid; i < T_LEN * NFREQ; i += blockDim.x) {
        int n = i / NFREQ, k = i % NFREQ;
        double ang = 2.0 * (double)(k * n) / 21.0;
        g_tw[2 * i]     = (float)cospi(ang);
        g_tw[2 * i + 1] = (float)(-sinpi(ang));
    }

    if (tid < T_LEN) {
        float a[21];
        #pragma unroll
        for (int i = 0; i < 21; i++) a[i] = (i == tid) ? 1.f : 0.f;
        int n = 21;
        const int rowbase[4] = {32, 22, 14, 7};
        for (int lev = 0; lev < 4; lev++) {
            int mout = (n + 5) / 2 + 1;
            float cA[14];
            for (int m = 0; m < mout; m++) {
                float aL = 0.f, aH = 0.f;
                #pragma unroll
                for (int j = 0; j < 8; j++) {
                    int idx = 2 * m + 1 - j;
                    if (idx < 0)  idx = -idx - 1;
                    if (idx >= n) idx = 2 * n - 1 - idx;
                    aL += c_lo[j] * a[idx];
                    aH += c_hi[j] * a[idx];
                }
                cA[m] = aL;
                g_L[(rowbase[lev] + m) * T_LEN + tid] = aH;
            }
            for (int m = 0; m < mout; m++) a[m] = cA[m];
            n = mout;
        }
        for (int m = 0; m < n; m++)
            g_L[m * T_LEN + tid] = a[m];
    }
    __syncthreads();

    for (int idx = tid; idx < NCH * 32; idx += blockDim.x) {
        int ci = idx >> 5, cp = idx & 31;
        float vlo[3], vhi[3];
        #pragma unroll
        for (int k = 0; k < 3; k++) {
            float a = conv_w[(cp * 78 + ci) * 3 + k];
            float b = conv_w[((cp + 32) * 78 + ci) * 3 + k];
            if (ci < T_LEN) {
                for (int j = 0; j < NWROWS; j++) {
                    float l = g_L[j * T_LEN + ci];
                    a += conv_w[(cp * 78 + 32 + j) * 3 + k] * l;
                    b += conv_w[((cp + 32) * 78 + 32 + j) * 3 + k] * l;
                }
            }
            vlo[k] = a; vhi[k] = b;
        }
        ulonglong2 w01;
        w01.x = pk2(vlo[0], vhi[0]);
        w01.y = pk2(vlo[1], vhi[1]);
        g_w01[idx] = w01;
        g_w2v[idx] = pk2(vlo[2], vhi[2]);
    }
}

/* ============ K1: feat[b][ch][s] = [x(21), |rfft|(11)] =================== */
__global__ void __launch_bounds__(128) feat_kernel(const float* __restrict__ x)
{
    __shared__ float sx[128 * T_LEN];
    __shared__ float stw[T_LEN * NFREQ * 2];

    int b  = blockIdx.x >> 3;
    int s0 = (blockIdx.x & 7) << 7;
    int tid = threadIdx.x;

    for (int i = tid; i < 128 * T_LEN; i += 128)
        sx[i] = x[(size_t)(b * S_LEN + s0) * T_LEN + i];
    for (int i = tid; i < T_LEN * NFREQ * 2; i += 128)
        stw[i] = g_tw[i];
    __syncthreads();

    float xr[T_LEN];
    #pragma unroll
    for (int i = 0; i < T_LEN; i++) xr[i] = sx[tid * T_LEN + i];

    int s = s0 + tid;
    float* fb = g_feat + (size_t)b * NCH * S_LEN + s;
    #pragma unroll
    for (int i = 0; i < T_LEN; i++) fb[i * S_LEN] = xr[i];

    for (int k = 0; k < NFREQ; k++) {
        float re = 0.f, im = 0.f;
        #pragma unroll
        for (int n = 0; n < T_LEN; n++) {
            float cw = stw[(n * NFREQ + k) * 2];
            float sw = stw[(n * NFREQ + k) * 2 + 1];
            re = fmaf(xr[n], cw, re);
            im = fmaf(xr[n], sw, im);
        }
        fb[(T_LEN + k) * S_LEN] = sqrtf(re * re + im * im);
    }
}

/* ============ K2: conv3 + ReLU + maxpool2, FFMA2 channel pairs =========== */
__global__ void __launch_bounds__(512) conv_pool2_kernel(const float* __restrict__ conv_b)
{
    extern __shared__ u64t sm2[];
    u64t*       sdup = sm2;
    ulonglong2* sw01 = (ulonglong2*)(sm2 + NCH * ROWP2);
    u64t*       sw2v = (u64t*)(sw01 + NCH * 32);

    int tid = threadIdx.x;
    int b   = blockIdx.x >> 2;
    int s0  = (blockIdx.x & 3) * 256;
    int cp  = tid & 31;
    int sg  = tid >> 5;
    int cs  = sg * 16;

    const float* fb = g_feat + (size_t)b * NCH * S_LEN;
    for (int i = tid; i < NCH * 258; i += 512) {
        int ci = i / 258, col = i % 258;
        int s = s0 + col - 1;
        float v = (s >= 0 && s < S_LEN) ? fb[ci * S_LEN + s] : 0.f;
        sdup[ci * ROWP2 + col] = pk2(v, v);
    }
    for (int i = tid; i < NCH * 32; i += 512) {
        sw01[i] = g_w01[i];
        sw2v[i] = g_w2v[i];
    }
    __syncthreads();

    u64t bias2 = pk2(conv_b[cp], conv_b[cp + 32]);
    u64t acc[16];
    #pragma unroll
    for (int i = 0; i < 16; i++) acc[i] = bias2;

    for (int ci = 0; ci < NCH; ci++) {
        const ulonglong2* vp = (const ulonglong2*)(sdup + ci * ROWP2 + cs);
        ulonglong2 w01 = sw01[ci * 32 + cp];
        u64t       wk2 = sw2v[ci * 32 + cp];
        u64t v[18];
        #pragma unroll
        for (int q = 0; q < 9; q++) {
            ulonglong2 t2 = vp[q];
            v[2 * q] = t2.x; v[2 * q + 1] = t2.y;
        }
        #pragma unroll
        for (int i = 0; i < 16; i++) {
            ffma2(acc[i], w01.x, v[i]);
            ffma2(acc[i], w01.y, v[i + 1]);
            ffma2(acc[i], wk2,   v[i + 2]);
        }
    }

    float* pout = g_pooled + (size_t)b * POOL_T * COUT;
    int t0 = (s0 + cs) >> 1;
    #pragma unroll
    for (int i = 0; i < 8; i++) {
        float l0, h0, l1, h1;
        upk2(acc[2 * i],     l0, h0);
        upk2(acc[2 * i + 1], l1, h1);
        pout[(t0 + i) * COUT + cp]      = fmaxf(fmaxf(l0, l1), 0.f);
        pout[(t0 + i) * COUT + cp + 32] = fmaxf(fmaxf(h0, h1), 0.f);
    }
}

/* ============ K2b: xg = pooled @ Wcol + bias, gate-prescaled ============= */
__global__ void __launch_bounds__(256) xg2_kernel(
    const float* __restrict__ w_ih, const float* __restrict__ b_ih,
    const float* __restrict__ b_hh)
{
    extern __shared__ u64t smw[];
    u64t*  sW = smw;
    float* sA = (float*)(smw + 64 * 66);

    int tid = threadIdx.x;
    size_t R0 = (size_t)blockIdx.x * XGT;

    for (int idx = tid; idx < 64 * 64; idx += 256) {
        int k = idx >> 6, cp = idx & 63;
        int j = cp >> 1, g0 = (cp & 1) * 2;
        float s0f = (cp & 1) ? TL2E : L2E;
        sW[k * 66 + cp] = pk2(w_ih[(g0 * 32 + j) * 64 + k] * s0f,
                              w_ih[((g0 + 1) * 32 + j) * 64 + k] * L2E);
    }

    const float* Ap = g_pooled + R0 * 64;
    for (int idx = tid; idx < XGT * 16; idx += 256) {
        int r = idx >> 4, q = idx & 15;
        float4 v = *(const float4*)(Ap + r * 64 + q * 4);
        sA[(4 * q + 0) * 132 + r] = v.x;
        sA[(4 * q + 1) * 132 + r] = v.y;
        sA[(4 * q + 2) * 132 + r] = v.z;
        sA[(4 * q + 3) * 132 + r] = v.w;
    }
    __syncthreads();

    int tx = tid & 15, ty = tid >> 4;
    int r0 = ty * 8;

    u64t acc[8][4];
    #pragma unroll
    for (int i = 0; i < 8; i++)
        #pragma unroll
        for (int q = 0; q < 4; q++) acc[i][q] = 0ull;

    #pragma unroll 4
    for (int k = 0; k < 64; k++) {
        const float* ar = sA + k * 132 + r0;
        float4 av0 = *(const float4*)ar;
        float4 av1 = *(const float4*)(ar + 4);
        u64t ad[8] = { pk2(av0.x, av0.x), pk2(av0.y, av0.y),
                       pk2(av0.z, av0.z), pk2(av0.w, av0.w),
                       pk2(av1.x, av1.x), pk2(av1.y, av1.y),
                       pk2(av1.z, av1.z), pk2(av1.w, av1.w) };
        const u64t* wr = sW + k * 66 + tx;
        u64t wv[4] = { wr[0], wr[16], wr[32], wr[48] };
        #pragma unroll
        for (int i = 0; i < 8; i++)
            #pragma unroll
            for (int q = 0; q < 4; q++)
                ffma2(acc[i][q], ad[i], wv[q]);
    }

    float* outp = g_xg + R0 * 128;
    #pragma unroll
    for (int q = 0; q < 4; q++) {
        int cp = tx + q * 16;
        int j = cp >> 1, g0 = (cp & 1) * 2;
        int gi0 = g0 * 32 + j, gi1 = (g0 + 1) * 32 + j;
        float s0f = (cp & 1) ? TL2E : L2E;
        u64t bp = pk2((b_ih[gi0] + b_hh[gi0]) * s0f,
                      (b_ih[gi1] + b_hh[gi1]) * L2E);
        #pragma unroll
        for (int i = 0; i < 8; i++) {
            u64t s = acc[i][q];
            fadd2(s, bp);
            float lo, hi;
            upk2(s, lo, hi);
            *(float2*)(outp + (size_t)(r0 + i) * 128 + cp * 2) = make_float2(lo, hi);
        }
    }
}

/* ============ K3: LSTM v6 — gate-split over 2 warps, 1 batch/CTA ========= */
/* warp0: gates (i,f); warp1: gates (g,o). One __syncthreads per step.       */
/* Both warps redundantly compute c,h; each keeps a private h broadcast buf. */
__global__ void __launch_bounds__(64) lstm6_kernel(
    const float* __restrict__ w_hh, const float* __restrict__ fc_w,
    const float* __restrict__ fc_b, float* __restrict__ out)
{
    __shared__ __align__(16) float  s_h[2][2][32];    /* [warp][buf][j] */
    __shared__ __align__(16) float2 s_act[2][2][32];  /* [warp][buf][j] */

    int w = threadIdx.x >> 5;      /* 0 or 1 */
    int j = threadIdx.x & 31;
    int b = blockIdx.x;

    /* weights for this warp's two gates, k-pair packed, prescaled */
    const float sc_all[4] = { L2E, L2E, TL2E, L2E };
    u64t w2[2][16];
    #pragma unroll
    for (int gl = 0; gl < 2; gl++) {
        int gg = w * 2 + gl;
        float s = sc_all[gg];
        const float4* row = (const float4*)(w_hh + (gg * 32 + j) * 32);
        #pragma unroll
        for (int q = 0; q < 8; q++) {
            float4 v = row[q];
            w2[gl][2 * q]     = pk2(v.x * s, v.y * s);
            w2[gl][2 * q + 1] = pk2(v.z * s, v.w * s);
        }
    }

    s_h[w][0][j] = 0.f;
    float c = 0.f, h = 0.f;

    /* this warp's xg stream: u64 (gate0, gate1) at floats [4j + 2w] */
    const float* xbase = g_xg + (size_t)b * POOL_T * 128 + 4 * j + 2 * w;
    u64t pre[4];
    #pragma unroll
    for (int u = 0; u < 4; u++)
        pre[u] = *(const u64t*)(xbase + (size_t)u * 128);
    __syncthreads();

    for (int t = 0; t < POOL_T; t += 4) {
        #pragma unroll
        for (int u = 0; u < 4; u++) {
            int tt = t + u;
            u64t xz = pre[u];
            int tn = tt + 4;
            if (tn > POOL_T - 1) tn = POOL_T - 1;
            pre[u] = *(const u64t*)(xbase + (size_t)tn * 128);

            const ulonglong2* hp = (const ulonglong2*)s_h[w][tt & 1];

            u64t a0 = xz & 0xffffffffull;   /* (x_g0, 0) */
            u64t a1 = xz >> 32;             /* (x_g1, 0) */
            u64t b0 = 0, b1 = 0, d0 = 0, d1 = 0, e0 = 0, e1 = 0;

            #pragma unroll
            for (int kq = 0; kq < 4; kq++) {
                ulonglong2 h2 = hp[kq];
                ffma2(a0, w2[0][2 * kq],     h2.x);
                ffma2(a1, w2[1][2 * kq],     h2.x);
                ffma2(d0, w2[0][2 * kq + 1], h2.y);
                ffma2(d1, w2[1][2 * kq + 1], h2.y);
            }
            #pragma unroll
            for (int kq = 4; kq < 8; kq++) {
                ulonglong2 h2 = hp[kq];
                ffma2(b0, w2[0][2 * kq],     h2.x);
                ffma2(b1, w2[1][2 * kq],     h2.x);
                ffma2(e0, w2[0][2 * kq + 1], h2.y);
                ffma2(e1, w2[1][2 * kq + 1], h2.y);
            }
            fadd2(a0, b0); fadd2(d0, e0); fadd2(a0, d0);
            fadd2(a1, b1); fadd2(d1, e1); fadd2(a1, d1);

            float lo, hi;
            upk2(a0, lo, hi); float z0 = lo + hi;
            upk2(a1, lo, hi); float z1 = lo + hi;

            float act0, act1;
            if (w == 0) { act0 = sig_p(z0);  act1 = sig_p(z1); }  /* ai, af */
            else        { act0 = tanh_p(z0); act1 = sig_p(z1); }  /* ag, ao */
            s_act[w][tt & 1][j] = make_float2(act0, act1);
            __syncthreads();

            float2 other = s_act[w ^ 1][tt & 1][j];
            float ai, af, ag, ao;
            if (w == 0) { ai = act0;   af = act1;   ag = other.x; ao = other.y; }
            else        { ai = other.x; af = other.y; ag = act0;  ao = act1;   }

            c = fmaf(af, c, ai * ag);
            h = ao * tanh_p(c * TL2E);
            s_h[w][(tt & 1) ^ 1][j] = h;
        }
    }

    if (w == 0) {
        float v = fc_w[j] * h;
        #pragma unroll
        for (int off = 16; off; off >>= 1)
            v += __shfl_down_sync(0xffffffffu, v, off);
        if (j == 0) out[b] = v + fc_b[0];
    }
}

/* ======================================================================== */
extern "C" void kernel_launch(void* const* d_in, const int* in_sizes, int n_in,
                              void* d_out, int out_size)
{
    const float* x      = (const float*)d_in[0];
    const float* conv_w = (const float*)d_in[1];
    const float* conv_b = (const float*)d_in[2];
    const float* w_ih   = (const float*)d_in[3];
    const float* w_hh   = (const float*)d_in[4];
    const float* b_ih   = (const float*)d_in[5];
    const float* b_hh   = (const float*)d_in[6];
    const float* fc_w   = (const float*)d_in[7];
    const float* fc_b   = (const float*)d_in[8];
    float* out = (float*)d_out;

    precompute_kernel<<<1, 256>>>(conv_w);
    feat_kernel<<<B_SZ * 8, 128>>>(x);

    size_t smem_c = (size_t)NCH * ROWP2 * 8 + (size_t)NCH * 32 * 24;
    cudaFuncSetAttribute(conv_pool2_kernel,
                         cudaFuncAttributeMaxDynamicSharedMemorySize, (int)smem_c);
    conv_pool2_kernel<<<B_SZ * 4, 512, smem_c>>>(conv_b);

    size_t smem_g = (size_t)(64 * 66) * sizeof(u64t) +
                    (size_t)(64 * 132) * sizeof(float);
    cudaFuncSetAttribute(xg2_kernel,
                         cudaFuncAttributeMaxDynamicSharedMemorySize, (int)smem_g);
    xg2_kernel<<<(B_SZ * POOL_T) / XGT, 256, smem_g>>>(w_ih, b_ih, b_hh);

    lstm6_kernel<<<B_SZ, 64>>>(w_hh, fc_w, fc_b, out);
}